// round 17
// baseline (speedup 1.0000x reference)
#include <cuda_runtime.h>
#include <cuda_bf16.h>
#include <math.h>
#include <stdint.h>

// Problem constants
#define B_  4096
#define T_  200
#define E_  64
#define GRID_MAIN 148   // 1 CTA per SM, double-buffered pipeline

// -------- device scratch (no allocations allowed) --------
__device__ float g_inter[B_ * 64];
__device__ unsigned int g_w1hi[64 * 256];
__device__ unsigned int g_w1lo[64 * 256];
__device__ unsigned int g_w2hi[128 * 128];
__device__ unsigned int g_w2lo[128 * 128];

// ---- bf16 helpers ----
__device__ __forceinline__ unsigned int pack_bf16(float lo, float hi) {
    unsigned int r;
    asm("cvt.rn.bf16x2.f32 %0, %1, %2;" : "=r"(r) : "f"(hi), "f"(lo));
    return r;
}
__device__ __forceinline__ void split2_bf16(float x0, float x1,
                                            unsigned int& hi, unsigned int& lo) {
    hi = pack_bf16(x0, x1);
    float h0 = __bfloat162float(__float2bfloat16(x0));
    float h1 = __bfloat162float(__float2bfloat16(x1));
    lo = pack_bf16(x0 - h0, x1 - h1);
}
__device__ __forceinline__ void mma_bf16(
    float& c0, float& c1, float& c2, float& c3,
    unsigned int a0, unsigned int a1, unsigned int a2, unsigned int a3,
    unsigned int b0, unsigned int b1) {
    asm("mma.sync.aligned.m16n8k16.row.col.f32.bf16.bf16.f32 "
        "{%0,%1,%2,%3},{%4,%5,%6,%7},{%8,%9},{%0,%1,%2,%3};"
        : "+f"(c0), "+f"(c1), "+f"(c2), "+f"(c3)
        : "r"(a0), "r"(a1), "r"(a2), "r"(a3), "r"(b0), "r"(b1));
}
// ---- cp.async helpers ----
__device__ __forceinline__ void cp_async16(unsigned int dst, const void* src) {
    asm volatile("cp.async.ca.shared.global [%0], [%1], 16;" :: "r"(dst), "l"(src) : "memory");
}
__device__ __forceinline__ void cp_async4(unsigned int dst, const void* src) {
    asm volatile("cp.async.ca.shared.global [%0], [%1], 4;" :: "r"(dst), "l"(src) : "memory");
}
__device__ __forceinline__ unsigned int smem_u32(const void* p) {
    return (unsigned int)__cvta_generic_to_shared(p);
}
#define CP_COMMIT() asm volatile("cp.async.commit_group;" ::: "memory")
#define CP_WAIT0()  asm volatile("cp.async.wait_group 0;" ::: "memory")
// ---- cp.async.bulk + mbarrier ----
__device__ __forceinline__ void cp_async_bulk(unsigned int dst, const void* src,
                                              unsigned int bytes, unsigned int mbar) {
    asm volatile(
        "cp.async.bulk.shared::cluster.global.mbarrier::complete_tx::bytes "
        "[%0], [%1], %2, [%3];"
        :: "r"(dst), "l"(src), "r"(bytes), "r"(mbar) : "memory");
}
__device__ __forceinline__ void mbar_init(unsigned int mbar, unsigned int count) {
    asm volatile("mbarrier.init.shared.b64 [%0], %1;" :: "r"(mbar), "r"(count) : "memory");
}
__device__ __forceinline__ void mbar_arrive_expect_tx(unsigned int mbar, unsigned int tx) {
    asm volatile("mbarrier.arrive.expect_tx.shared.b64 _, [%0], %1;"
                 :: "r"(mbar), "r"(tx) : "memory");
}
__device__ __forceinline__ void mbar_wait_parity(unsigned int mbar, unsigned int parity) {
    asm volatile(
        "{\n\t.reg .pred P1;\n\t"
        "WAIT_%=:\n\t"
        "mbarrier.try_wait.parity.acquire.cta.shared::cta.b64 P1, [%0], %1, 0x989680;\n\t"
        "@P1 bra DONE_%=;\n\t"
        "bra WAIT_%=;\n\t"
        "DONE_%=:\n\t}"
        :: "r"(mbar), "r"(parity) : "memory");
}

// ============================================================
// prep kernel: bf16x2 split of mw1 + mw2 into hi/lo planes
// ============================================================
__global__ void prep_w(const float* __restrict__ mw1, const float* __restrict__ mw2) {
    int idx = blockIdx.x * blockDim.x + threadIdx.x;
    if (idx < 16384) {
        int p = idx >> 8, n = idx & 255;
        float x0 = mw1[(2 * p) * 256 + n];
        float x1 = mw1[(2 * p + 1) * 256 + n];
        unsigned int hi, lo;
        split2_bf16(x0, x1, hi, lo);
        g_w1hi[idx] = hi;
        g_w1lo[idx] = lo;
    } else {
        int j = idx - 16384;
        int p = j >> 7, n = j & 127;
        float x0 = mw2[(2 * p) * 128 + n];
        float x1 = mw2[(2 * p + 1) * 128 + n];
        unsigned int hi, lo;
        split2_bf16(x0, x1, hi, lo);
        g_w2hi[j] = hi;
        g_w2lo[j] = lo;
    }
}

// ============================================================
// main kernel: PERSISTENT 148x512, 1 CTA/SM, cross-iteration
// software pipeline: HIST/MSK/NID double-buffered, QV prefetched.
// Steady state has ZERO memory waits on the critical path.
// ============================================================
#define PH  68
#define PWB 36
#define OFF_HIST0 0        // 14144
#define OFF_HIST1 14144    // -> 28288
#define OFF_WCB   28288    // 2304 -> 30592
#define OFF_W2B   30592    // 1152 -> 31744
#define OFF_QV    31744    // 64
#define OFF_QB    31808    // 64
#define OFF_AB2   31872    // 32
#define OFF_AOW   31904    // 32
#define OFF_SC    31936    // 208
#define OFF_MSK0  32144    // 208
#define OFF_MSK1  32352    // 208
#define OFF_WRED  32560    // 32
#define OFF_RED   32592    // 1024 -> 33616
#define OFF_WHPB  33616    // 4096 -> 37712
#define OFF_WQB   37712    // 2048 -> 39760
#define OFF_NID0  39760    // 208 -> 39968
#define OFF_NID1  39968    // 208 -> 40176
#define OFF_NTGT0 40176
#define OFF_NTGT1 40177
#define OFF_MBAR0 40178    // 8B aligned (40178*4 % 8 == 0)
#define OFF_MBAR1 40180
#define SMEM_B_FLOATS 40184
#define SMEM_B_BYTES  (SMEM_B_FLOATS * 4)

__global__ __launch_bounds__(512, 1) void din_main(
    const int* __restrict__ hist_id,
    const int* __restrict__ mask,
    const float* __restrict__ table,
    const int* __restrict__ target,
    const float* __restrict__ aw1,
    const float* __restrict__ ab1,
    const float* __restrict__ aw2,
    const float* __restrict__ ab2,
    const float* __restrict__ aow,
    const float* __restrict__ aob) {
    extern __shared__ float sm[];
    unsigned int* smu = (unsigned int*)sm;
    int* smi = (int*)sm;
    unsigned int* whpb = smu + OFF_WHPB;
    __nv_bfloat16* wqb = (__nv_bfloat16*)(smu + OFF_WQB);
    const int tid = threadIdx.x;
    const int w   = tid >> 5;
    const int l   = tid & 31;
    const int l4  = l >> 2;
    const int lm  = l & 3;
    const unsigned int mb0v = smem_u32(smu + OFF_MBAR0);
    const unsigned int mb1v = smem_u32(smu + OFF_MBAR1);

    // ---- loop-invariant staging ----
    if (tid < 32)        sm[OFF_AB2 + tid]      = ab2[tid];
    else if (tid < 64)   sm[OFF_AOW + tid - 32] = aow[tid - 32];
    for (int idx = tid; idx < 32 * 32; idx += 512) {
        int kp = idx & 31, n = idx >> 5;
        float v0 = aw2[(2 * kp) * 32 + n];
        float v1 = aw2[(2 * kp + 1) * 32 + n];
        smu[OFF_W2B + n * PWB + kp] = pack_bf16(v0, v1);
    }
    for (int idx = tid; idx < 64 * 64; idx += 512) {
        int k = idx & 63, n = idx >> 6;
        float a = aw1[k * 64 + n];
        float bb = aw1[(64 + k) * 64 + n];
        float c = aw1[(128 + k) * 64 + n];
        float d = aw1[(192 + k) * 64 + n];
        whpb[n * 64 + k] = pack_bf16(a + c, d);
        wqb[k * 64 + n] = __float2bfloat16(bb - c);
    }
    // zero-pad rows 200..207 in BOTH hist buffers (once)
    {
        for (int idx = tid; idx < 8 * 17; idx += 512) {
            int t = 200 + idx / 17, v = idx % 17;
            ((float4*)(sm + OFF_HIST0))[t * 17 + v] = make_float4(0.f, 0.f, 0.f, 0.f);
            ((float4*)(sm + OFF_HIST1))[t * 17 + v] = make_float4(0.f, 0.f, 0.f, 0.f);
        }
    }
    // first-batch IDs/target (plain), mbar init
    if (tid < 200) smi[OFF_NID0 + tid] = hist_id[(size_t)blockIdx.x * T_ + tid];
    if (tid == 256) smi[OFF_NTGT0] = target[blockIdx.x];
    if (tid == 0) { mbar_init(mb0v, 200); mbar_init(mb1v, 200); }
    const float aob0 = aob[0];
    const float ab1v = (tid < 64) ? ab1[tid] : 0.f;
    __syncthreads();   // NID0/NTGT0/mbars visible

    // ---- prologue: gather batch b0 -> HIST0; group: QV0/MSK0/NID1/NTGT1 ----
    if (tid < T_) {
        mbar_arrive_expect_tx(mb0v, 256);
        cp_async_bulk(smem_u32(sm + OFF_HIST0 + tid * PH),
                      table + (size_t)smi[OFF_NID0 + tid] * 64, 256, mb0v);
    }
    {
        int b0i = blockIdx.x;
        int nb = b0i + GRID_MAIN;   // always < B_
        if (tid < 16)
            cp_async16(smem_u32(sm + OFF_QV + tid * 4),
                       (const float4*)table + (size_t)smi[OFF_NTGT0] * 16 + tid);
        else if (tid < 66)
            cp_async16(smem_u32(smi + OFF_MSK0 + (tid - 16) * 4),
                       (const int4*)(mask + (size_t)b0i * T_) + (tid - 16));
        else if (tid < 116)
            cp_async16(smem_u32(smi + OFF_NID1 + (tid - 66) * 4),
                       (const int4*)(hist_id + (size_t)nb * T_) + (tid - 66));
        else if (tid == 116)
            cp_async4(smem_u32(smi + OFF_NTGT1), target + nb);
        CP_COMMIT();
    }

    unsigned int ph0 = 0, ph1 = 0;
    int it = 0;
    for (int b = blockIdx.x; b < B_; b += GRID_MAIN, ++it) {
        CP_WAIT0();        // prefetch group landed (QV/MSK[nxt]/NID/NTGT)
        __syncthreads();   // B0: visible; prior iter's HIST[nxt] reads done

        const int cur = it & 1;
        const float* hist = sm + (cur ? OFF_HIST1 : OFF_HIST0);
        float* histN = sm + (cur ? OFF_HIST0 : OFF_HIST1);
        const int* mskp = smi + (cur ? OFF_MSK1 : OFF_MSK0);
        const int* nidN = smi + (cur ? OFF_NID0 : OFF_NID1);
        const unsigned int mb_cur = cur ? mb1v : mb0v;
        const unsigned int mb_nxt = cur ? mb0v : mb1v;
        const int nb  = b + GRID_MAIN;
        const int nnb = b + 2 * GRID_MAIN;

        // --- issue NEXT gather (covered by this whole iteration) ---
        if (nb < B_ && tid < T_) {
            mbar_arrive_expect_tx(mb_nxt, 256);
            cp_async_bulk(smem_u32(histN + tid * PH),
                          table + (size_t)nidN[tid] * 64, 256, mb_nxt);
        }

        // --- qb partials (QV already resident) ---
        {
            int n = tid & 63, kc = tid >> 6;
            float acc = 0.f;
#pragma unroll
            for (int i = 0; i < 8; ++i) {
                int k = kc * 8 + i;
                acc = fmaf(sm[OFF_QV + k], __bfloat162float(wqb[k * 64 + n]), acc);
            }
            sm[OFF_RED + kc * 64 + n] = acc;
        }
        __syncthreads();   // B1.5
        if (tid < 64) {
            float acc = ab1v;
#pragma unroll
            for (int kc = 0; kc < 8; ++kc) acc += sm[OFF_RED + kc * 64 + tid];
            sm[OFF_QB + tid] = acc;
        }
        // --- fold Wc -> bf16 pairs ---
        for (int idx = tid; idx < 64 * 32; idx += 512) {
            int kp = idx & 31, n = idx >> 5;
            uint2 hp2 = *(const uint2*)(whpb + n * 64 + 2 * kp);
            __nv_bfloat162 h0 = *(__nv_bfloat162*)&hp2.x;
            __nv_bfloat162 h1 = *(__nv_bfloat162*)&hp2.y;
            float f0 = fmaf(sm[OFF_QV + 2 * kp],     __bfloat162float(h0.y),
                            __bfloat162float(h0.x));
            float f1 = fmaf(sm[OFF_QV + 2 * kp + 1], __bfloat162float(h1.y),
                            __bfloat162float(h1.x));
            smu[OFF_WCB + n * PWB + kp] = pack_bf16(f0, f1);
        }
        __syncthreads();   // B2: QB/WCB visible; QV free for rewrite

        // --- prefetch group for iter+1: QV[nb], MSK[nxt], NID[cur]<-nnb ---
        if (nb < B_) {
            int ntgt_n = smi[cur ? OFF_NTGT1 : OFF_NTGT0 + 0];
            // (NTGT for nb lives in the *other* slot: written two iters ago)
            ntgt_n = smi[(cur ? OFF_NTGT0 : OFF_NTGT1)];
            if (tid < 16)
                cp_async16(smem_u32(sm + OFF_QV + tid * 4),
                           (const float4*)table + (size_t)ntgt_n * 16 + tid);
            else if (tid < 66)
                cp_async16(smem_u32((int*)mskp + (tid - 16) * 4 - 0) +
                               0 * 0,   // MSK[nxt] slot == mskp's opposite
                           (const int4*)(mask + (size_t)nb * T_) + (tid - 16));
            // NOTE: mskp points at CURRENT; next slot is the other one:
        }
        // (rewritten cleanly below)
        if (nb < B_) {
            int* msk_next = smi + (cur ? OFF_MSK0 : OFF_MSK1);
            int* nid_self = smi + (cur ? OFF_NID1 : OFF_NID0);
            if (tid >= 200 && tid < 250 && nnb < B_)
                cp_async16(smem_u32(nid_self + (tid - 200) * 4),
                           (const int4*)(hist_id + (size_t)nnb * T_) + (tid - 200));
            else if (tid == 250 && nnb < B_)
                cp_async4(smem_u32(smi + (cur ? OFF_NTGT1 : OFF_NTGT0)), target + nnb);
            else if (tid >= 134 && tid < 184)
                cp_async16(smem_u32(msk_next + (tid - 134) * 4),
                           (const int4*)(mask + (size_t)nb * T_) + (tid - 134));
        }
        CP_COMMIT();

        // --- wait for CURRENT gather (was issued a full iteration ago) ---
        mbar_wait_parity(mb_cur, cur ? ph1 : ph0);
        if (cur) ph1 ^= 1; else ph0 ^= 1;

        // ====== fused attention MLP (bf16 k16): warps 0..12 ======
        if (w < 13) {
            const int mt = w;

            unsigned int a[4][4];
            {
                const float* abase = hist + (mt * 16 + l4) * PH + 2 * lm;
#pragma unroll
                for (int ks = 0; ks < 4; ++ks) {
                    float2 v00 = *(const float2*)(abase + 16 * ks);
                    float2 v10 = *(const float2*)(abase + 16 * ks + 8 * PH);
                    float2 v01 = *(const float2*)(abase + 16 * ks + 8);
                    float2 v11 = *(const float2*)(abase + 16 * ks + 8 * PH + 8);
                    a[ks][0] = pack_bf16(v00.x, v00.y);
                    a[ks][1] = pack_bf16(v10.x, v10.y);
                    a[ks][2] = pack_bf16(v01.x, v01.y);
                    a[ks][3] = pack_bf16(v11.x, v11.y);
                }
            }

            float d0[4], d1[4], d2[4], d3[4];
#pragma unroll
            for (int nt = 0; nt < 4; ++nt) {
                float bb0 = sm[OFF_AB2 + nt * 8 + 2 * lm];
                float bb1 = sm[OFF_AB2 + nt * 8 + 2 * lm + 1];
                d0[nt] = bb0; d1[nt] = bb1; d2[nt] = bb0; d3[nt] = bb1;
            }

            const unsigned int* wcbw = smu + OFF_WCB + l4 * PWB + lm;
            const unsigned int* w2bw = smu + OFF_W2B + l4 * PWB + lm;

#pragma unroll
            for (int j = 0; j < 4; ++j) {
                unsigned int A2[4];
#pragma unroll
                for (int t2 = 0; t2 < 2; ++t2) {
                    const int kk = 2 * j + t2;
                    float c0 = sm[OFF_QB + kk * 8 + 2 * lm];
                    float c1 = sm[OFF_QB + kk * 8 + 2 * lm + 1];
                    float c2 = c0, c3 = c1;
                    const unsigned int* wb = wcbw + kk * 8 * PWB;
#pragma unroll
                    for (int ks = 0; ks < 4; ++ks) {
                        unsigned int b0 = wb[8 * ks];
                        unsigned int b1 = wb[8 * ks + 4];
                        mma_bf16(c0, c1, c2, c3,
                                 a[ks][0], a[ks][1], a[ks][2], a[ks][3], b0, b1);
                    }
                    A2[2 * t2 + 0] = pack_bf16(fmaxf(c0, 0.f), fmaxf(c1, 0.f));
                    A2[2 * t2 + 1] = pack_bf16(fmaxf(c2, 0.f), fmaxf(c3, 0.f));
                }
                const unsigned int* w2 = w2bw + 8 * j;
#pragma unroll
                for (int nt = 0; nt < 4; ++nt) {
                    unsigned int b0 = w2[nt * 8 * PWB];
                    unsigned int b1 = w2[nt * 8 * PWB + 4];
                    mma_bf16(d0[nt], d1[nt], d2[nt], d3[nt],
                             A2[0], A2[1], A2[2], A2[3], b0, b1);
                }
            }

            float p01 = 0.f, p23 = 0.f;
#pragma unroll
            for (int nt = 0; nt < 4; ++nt) {
                float w0 = sm[OFF_AOW + nt * 8 + 2 * lm];
                float w1 = sm[OFF_AOW + nt * 8 + 2 * lm + 1];
                p01 = fmaf(fmaxf(d0[nt], 0.f), w0, fmaf(fmaxf(d1[nt], 0.f), w1, p01));
                p23 = fmaf(fmaxf(d2[nt], 0.f), w0, fmaf(fmaxf(d3[nt], 0.f), w1, p23));
            }
            p01 += __shfl_xor_sync(0xffffffffu, p01, 1);
            p01 += __shfl_xor_sync(0xffffffffu, p01, 2);
            p23 += __shfl_xor_sync(0xffffffffu, p23, 1);
            p23 += __shfl_xor_sync(0xffffffffu, p23, 2);
            float e01 = 0.f, e23 = 0.f;
            if (lm == 0) {
                int r0 = mt * 16 + l4;
                int r1 = r0 + 8;
                e01 = (mskp[r0] != 0) ? __expf(p01 + aob0) : 0.f;
                sm[OFF_SC + r0] = e01;
                if (r1 < T_) {
                    e23 = (mskp[r1] != 0) ? __expf(p23 + aob0) : 0.f;
                    sm[OFF_SC + r1] = e23;
                }
            }
            float esum = e01 + e23;
            esum += __shfl_xor_sync(0xffffffffu, esum, 16);
            esum += __shfl_xor_sync(0xffffffffu, esum, 8);
            esum += __shfl_xor_sync(0xffffffffu, esum, 4);
            esum += __shfl_xor_sync(0xffffffffu, esum, 2);
            esum += __shfl_xor_sync(0xffffffffu, esum, 1);
            if (l == 0) sm[OFF_WRED + w] = esum;
        }
        __syncthreads();   // B3

        // ---- interest (float2, 16 warp-groups; normalization folded) ----
        {
            float ss = 0.f;
#pragma unroll
            for (int i = 0; i < 13; ++i) ss += sm[OFF_WRED + i];
            float inv = 1.f / ss;
            int j2 = (tid & 31) * 2, g = w;
            int tb = (g * 200) >> 4, te = ((g + 1) * 200) >> 4;
            float ax = 0.f, ay = 0.f;
            for (int t = tb; t < te; ++t) {
                float wt = sm[OFF_SC + t];
                float2 h = *(const float2*)(hist + t * PH + j2);
                ax = fmaf(wt, h.x, ax);
                ay = fmaf(wt, h.y, ay);
            }
            sm[OFF_RED + g * 64 + j2]     = ax * inv;
            sm[OFF_RED + g * 64 + j2 + 1] = ay * inv;
        }
        __syncthreads();   // B6
        if (tid < 64) {
            float iv = 0.f;
#pragma unroll
            for (int g = 0; g < 16; ++g) iv += sm[OFF_RED + g * 64 + tid];
            g_inter[b * 64 + tid] = iv;
        }
    }
}

// ============================================================
// final MLP v6 (unchanged): bf16x2 pre-split weights.
// ============================================================
#define DR   16
#define FPX  136
#define P1P  264
#define P2P  136
#define PG1  132
#define FX    0
#define FG1H  2176
#define FG1L  4288
#define FWT0  6400
#define FWT1  14848
#define FMB1  23296
#define FMB2  23552
#define FOW   23680
#define FRED  23808
#define FTGT  23936
#define SMEM_F_FLOATS 23952
#define SMEM_F_BYTES  (SMEM_F_FLOATS * 4)
#define LOOFF 4224

__global__ __launch_bounds__(256, 2) void din_final(
    const int* __restrict__ target,
    const float* __restrict__ table,
    const float* __restrict__ mb1, const float* __restrict__ mb2,
    const float* __restrict__ ow,  const float* __restrict__ ob,
    float* __restrict__ out) {
    extern __shared__ float sm[];
    unsigned int* smu = (unsigned int*)sm;
    int* smi = (int*)sm;
    const int tid = threadIdx.x;
    const int w   = tid >> 5;
    const int l   = tid & 31;
    const int l4  = l >> 2;
    const int lm  = l & 3;
    const int b0  = blockIdx.x * DR;

    if (tid < DR) smi[FTGT + tid] = target[b0 + tid];
    sm[FMB1 + tid] = mb1[tid];
    if (tid < 128) { sm[FMB2 + tid] = mb2[tid]; sm[FOW + tid] = ow[tid]; }
    __syncthreads();

    {
        const float4* tab4 = (const float4*)table;
        const float4* int4p = (const float4*)g_inter;
        for (int idx = tid; idx < DR * 32; idx += 256) {
            int rr = idx >> 5, v = idx & 31;
            float4 x = (v < 16)
                ? tab4[(size_t)smi[FTGT + rr] * 16 + v]
                : int4p[(size_t)(b0 + rr) * 16 + (v - 16)];
            *(float4*)(sm + FX + rr * FPX + v * 4) = x;
        }
    }

    {
        const uint4* srcH = (const uint4*)g_w1hi;
        const uint4* srcL = (const uint4*)g_w1lo;
        unsigned int* dst = smu + FWT0;
        for (int idx = tid; idx < 1024; idx += 256) {
            int r = idx >> 6, v = idx & 63;
            cp_async16(smem_u32(dst + r * P1P + v * 4), srcH + r * 64 + v);
            cp_async16(smem_u32(dst + LOOFF + r * P1P + v * 4), srcL + r * 64 + v);
        }
        CP_COMMIT();
    }

    const int n0w  = w * 32;
    const int n0w2 = w * 16;
    float acc1[16], acc2[8];

    for (int c = 0; c < 12; ++c) {
        CP_WAIT0();
        __syncthreads();

        if (c < 11) {
            int nc = c + 1;
            unsigned int* dst = smu + ((nc & 1) ? FWT1 : FWT0);
            if (nc < 4) {
                const uint4* srcH = (const uint4*)g_w1hi + nc * 1024;
                const uint4* srcL = (const uint4*)g_w1lo + nc * 1024;
                for (int idx = tid; idx < 1024; idx += 256) {
                    int r = idx >> 6, v = idx & 63;
                    cp_async16(smem_u32(dst + r * P1P + v * 4), srcH + r * 64 + v);
                    cp_async16(smem_u32(dst + LOOFF + r * P1P + v * 4), srcL + r * 64 + v);
                }
            } else {
                const uint4* srcH = (const uint4*)g_w2hi + (nc - 4) * 512;
                const uint4* srcL = (const uint4*)g_w2lo + (nc - 4) * 512;
                for (int idx = tid; idx < 512; idx += 256) {
                    int r = idx >> 5, v = idx & 31;
                    cp_async16(smem_u32(dst + r * P2P + v * 4), srcH + r * 32 + v);
                    cp_async16(smem_u32(dst + LOOFF + r * P2P + v * 4), srcL + r * 32 + v);
                }
            }
            CP_COMMIT();
        }

        const unsigned int* wth = smu + ((c & 1) ? FWT1 : FWT0);
        const unsigned int* wtl = wth + LOOFF;

        if (c == 0) {
#pragma unroll
            for (int nt = 0; nt < 4; ++nt) {
                float bb0 = sm[FMB1 + n0w + nt * 8 + 2 * lm];
                float bb1 = sm[FMB1 + n0w + nt * 8 + 2 * lm + 1];
                acc1[nt * 4 + 0] = bb0; acc1[nt * 4 + 1] = bb1;
                acc1[nt * 4 + 2] = bb0; acc1[nt * 4 + 3] = bb1;
            }
        }
        if (c == 4) {
#pragma unroll
            for (int nt = 0; nt < 2; ++nt) {
                float bb0 = sm[FMB2 + n0w2 + nt * 8 + 2 * lm];
                float bb1 = sm[FMB2 + n0w2 + nt * 8 + 2 * lm + 1];
                acc2[nt * 4 + 0] = bb0; acc2[nt * 4 + 1] = bb1;
                acc2[nt * 4 + 2] = bb0; acc2[nt * 4 + 3] = bb1;
            }
        }

        if (c < 4) {
#pragma unroll
            for (int s = 0; s < 2; ++s) {
                const float* xb = sm + FX + l4 * FPX + c * 32 + s * 16 + 2 * lm;
                float2 xa = *(const float2*)(xb);
                float2 xbv = *(const float2*)(xb + 8 * FPX);
                float2 xc = *(const float2*)(xb + 8);
                float2 xd = *(const float2*)(xb + 8 * FPX + 8);
                unsigned int ah0, al0, ah1, al1, ah2, al2, ah3, al3;
                split2_bf16(xa.x,  xa.y,  ah0, al0);
                split2_bf16(xbv.x, xbv.y, ah1, al1);
                split2_bf16(xc.x,  xc.y,  ah2, al2);
                split2_bf16(xd.x,  xd.y,  ah3, al3);
#pragma unroll
                for (int nt = 0; nt < 4; ++nt) {
                    int bo = (s * 8 + lm) * P1P + n0w + nt * 8 + l4;
                    unsigned int b0h = wth[bo], b1h = wth[bo + 4 * P1P];
                    unsigned int b0l = wtl[bo], b1l = wtl[bo + 4 * P1P];
                    int base = nt * 4;
                    mma_bf16(acc1[base + 0], acc1[base + 1], acc1[base + 2], acc1[base + 3],
                             ah0, ah1, ah2, ah3, b0h, b1h);
                    mma_bf16(acc1[base + 0], acc1[base + 1], acc1[base + 2], acc1[base + 3],
                             al0, al1, al2, al3, b0h, b1h);
                    mma_bf16(acc1[base + 0], acc1[base + 1], acc1[base + 2], acc1[base + 3],
                             ah0, ah1, ah2, ah3, b0l, b1l);
                }
            }
            if (c == 3) {
#pragma unroll
                for (int nt = 0; nt < 4; ++nt) {
                    int base = nt * 4;
                    int kp = (n0w >> 1) + nt * 4 + lm;
                    float r0 = fmaxf(acc1[base + 0], 0.f);
                    float r1 = fmaxf(acc1[base + 1], 0.f);
                    float r2 = fmaxf(acc1[base + 2], 0.f);
                    float r3 = fmaxf(acc1[base + 3], 0.f);
                    unsigned int hw, lw;
                    split2_bf16(r0, r1, hw, lw);
                    smu[FG1H + l4 * PG1 + kp] = hw;
                    smu[FG1L + l4 * PG1 + kp] = lw;
                    split2_bf16(r2, r3, hw, lw);
                    smu[FG1H + (l4 + 8) * PG1 + kp] = hw;
                    smu[FG1L + (l4 + 8) * PG1 + kp] = lw;
                }
            }
        } else {
            int ck = c - 4;
#pragma unroll
            for (int s = 0; s < 2; ++s) {
                int kb = ck * 16 + s * 8 + lm;
                unsigned int ah0 = smu[FG1H + l4 * PG1 + kb];
                unsigned int ah1 = smu[FG1H + (l4 + 8) * PG1 + kb];
                unsigned int ah2 = smu[FG1H + l4 * PG1 + kb + 4];
                unsigned int ah3 = smu[FG1H + (l4 + 8) * PG1 + kb + 4];
                unsigned int al0 = smu[FG1L + l4 * PG1 + kb];
                unsigned int al1 = smu[FG1L + (l4 + 8) * PG1 + kb];
                unsigned int al2 = smu[FG1L + l4 * PG1 + kb + 4];
                unsigned int al3 = smu[FG1L + (l4 + 8) * PG1 + kb + 4];
#pragma unroll
                for (int nt = 0; nt < 2; ++nt) {
                    int bo = (s * 8 + lm) * P2P + n0w2 + nt * 8 + l4;
                    unsigned int b0h = wth[bo], b1h = wth[bo + 4 * P2P];
                    unsigned int b0l = wtl[bo], b1l = wtl[bo + 4 * P2P];
                    int base = nt * 4;
                    mma_bf16(acc2[base + 0], acc2[base + 1], acc2[base + 2], acc2[base + 3],
                             ah0, ah1, ah2, ah3, b0h, b1h);
                    mma_bf16(acc2[base + 0], acc2[base + 1], acc2[base + 2], acc2[base + 3],
                             al0, al1, al2, al3, b0h, b1h);
                    mma_bf16(acc2[base + 0], acc2[base + 1], acc2[base + 2], acc2[base + 3],
                             ah0, ah1, ah2, ah3, b0l, b1l);
                }
            }
        }
    }

    float pA = 0.f, pB = 0.f;
#pragma unroll
    for (int nt = 0; nt < 2; ++nt) {
        int base = nt * 4;
        float w0 = sm[FOW + n0w2 + nt * 8 + 2 * lm];
        float w1 = sm[FOW + n0w2 + nt * 8 + 2 * lm + 1];
        pA = fmaf(fmaxf(acc2[base + 0], 0.f), w0,
             fmaf(fmaxf(acc2[base + 1], 0.f), w1, pA));
        pB = fmaf(fmaxf(acc2[base + 2], 0.f), w0,
             fmaf(fmaxf(acc2[base + 3], 0.f), w1, pB));
    }
    pA += __shfl_xor_sync(0xffffffffu, pA, 1);
    pA += __shfl_xor_sync(0xffffffffu, pA, 2);
    pB += __shfl_xor_sync(0xffffffffu, pB, 1);
    pB += __shfl_xor_sync(0xffffffffu, pB, 2);
    if (lm == 0) {
        sm[FRED + w * 16 + l4]     = pA;
        sm[FRED + w * 16 + l4 + 8] = pB;
    }
    __syncthreads();
    if (tid < DR) {
        float p = ob[0];
#pragma unroll
        for (int w8 = 0; w8 < 8; ++w8) p += sm[FRED + w8 * 16 + tid];
        out[b0 + tid] = p;
    }
}

// ============================================================
// launch
// ============================================================
extern "C" void kernel_launch(void* const* d_in, const int* in_sizes, int n_in,
                              void* d_out, int out_size) {
    const int*   target  = (const int*)d_in[0];
    const int*   hist_id = (const int*)d_in[1];
    const int*   mask    = (const int*)d_in[2];
    const float* table   = (const float*)d_in[3];
    const float* aw1     = (const float*)d_in[4];
    const float* ab1     = (const float*)d_in[5];
    const float* aw2     = (const float*)d_in[6];
    const float* ab2     = (const float*)d_in[7];
    const float* aow     = (const float*)d_in[8];
    const float* aob     = (const float*)d_in[9];
    const float* mw1     = (const float*)d_in[10];
    const float* mb1     = (const float*)d_in[11];
    const float* mw2     = (const float*)d_in[12];
    const float* mb2     = (const float*)d_in[13];
    const float* ow      = (const float*)d_in[14];
    const float* ob      = (const float*)d_in[15];
    float* out = (float*)d_out;

    cudaFuncSetAttribute(din_main, cudaFuncAttributeMaxDynamicSharedMemorySize, SMEM_B_BYTES);
    cudaFuncSetAttribute(din_final, cudaFuncAttributeMaxDynamicSharedMemorySize, SMEM_F_BYTES);

    prep_w<<<64, 512>>>(mw1, mw2);
    din_main<<<GRID_MAIN, 512, SMEM_B_BYTES>>>(hist_id, mask, table, target, aw1,
                                               ab1, aw2, ab2, aow, aob);
    din_final<<<B_ / DR, 256, SMEM_F_BYTES>>>(target, table, mb1, mb2, ow, ob, out);
}